// round 3
// baseline (speedup 1.0000x reference)
#include <cuda_runtime.h>
#include <math.h>

#define N_TOK 8192
#define D_DIM 1024
#define TIME_DECAY_F 86400.0f
#define EPS_F 1e-10f
#define SCALE_INV (1.0f / 32.0f)   // 1/sqrt(1024)

// ---- scratch (no allocations allowed) ----
__device__ float g_Q[(size_t)N_TOK * D_DIM];
__device__ float g_K[(size_t)N_TOK * D_DIM];
__device__ float g_V[(size_t)N_TOK * D_DIM];
__device__ float g_S[(size_t)N_TOK * N_TOK];

// ============================================================
// GEMM NT: C[M,Nc] = A[M,K] @ B[Nc,K]^T  (both row-major)
// MODE 0: epilogue adds bias[n]          (QKV projections)
// MODE 1: epilogue acc/32 + log(exp(-|ti-tj|/TD)+eps)  (scores)
// Tiles: BM=BN=128, BK=8, 256 threads, 8x8 per thread.
// ============================================================
template <int MODE>
__global__ __launch_bounds__(256)
void gemm_nt(const float* __restrict__ A,
             const float* __restrict__ B,
             const float* __restrict__ aux,   // bias[Nc] (MODE 0) or timestamps[] (MODE 1)
             float* __restrict__ C,
             int M, int Nc, int K)
{
    __shared__ float As[8][128];
    __shared__ float Bs[8][128];

    const int tid = threadIdx.x;
    const int tx = tid & 15;          // 0..15
    const int ty = tid >> 4;          // 0..15
    const int bm = blockIdx.y * 128;
    const int bn = blockIdx.x * 128;

    const int ldRow = tid >> 1;       // 0..127
    const int ldCol = (tid & 1) * 4;  // 0 or 4

    const float* Aptr = A + (size_t)(bm + ldRow) * K + ldCol;
    const float* Bptr = B + (size_t)(bn + ldRow) * K + ldCol;

    float acc[8][8];
#pragma unroll
    for (int i = 0; i < 8; i++)
#pragma unroll
        for (int j = 0; j < 8; j++) acc[i][j] = 0.0f;

    for (int k0 = 0; k0 < K; k0 += 8) {
        float4 a4 = *(const float4*)(Aptr + k0);
        float4 b4 = *(const float4*)(Bptr + k0);
        As[ldCol + 0][ldRow] = a4.x;
        As[ldCol + 1][ldRow] = a4.y;
        As[ldCol + 2][ldRow] = a4.z;
        As[ldCol + 3][ldRow] = a4.w;
        Bs[ldCol + 0][ldRow] = b4.x;
        Bs[ldCol + 1][ldRow] = b4.y;
        Bs[ldCol + 2][ldRow] = b4.z;
        Bs[ldCol + 3][ldRow] = b4.w;
        __syncthreads();

#pragma unroll
        for (int k = 0; k < 8; k++) {
            float ra[8], rb[8];
#pragma unroll
            for (int i = 0; i < 8; i++) ra[i] = As[k][ty * 8 + i];
#pragma unroll
            for (int j = 0; j < 8; j++) rb[j] = Bs[k][tx * 8 + j];
#pragma unroll
            for (int i = 0; i < 8; i++)
#pragma unroll
                for (int j = 0; j < 8; j++)
                    acc[i][j] = fmaf(ra[i], rb[j], acc[i][j]);
        }
        __syncthreads();
    }

    if (MODE == 0) {
        // C = acc + bias[n]
        float bb[8];
#pragma unroll
        for (int j = 0; j < 8; j++) bb[j] = aux[bn + tx * 8 + j];
#pragma unroll
        for (int i = 0; i < 8; i++) {
            size_t rowoff = (size_t)(bm + ty * 8 + i) * Nc + bn + tx * 8;
#pragma unroll
            for (int j = 0; j < 8; j++)
                C[rowoff + j] = acc[i][j] + bb[j];
        }
    } else {
        // scores epilogue: acc/32 + log(exp(-|ti - tj|/TD) + eps)
        float ti[8], tj[8];
#pragma unroll
        for (int i = 0; i < 8; i++) ti[i] = aux[bm + ty * 8 + i];
#pragma unroll
        for (int j = 0; j < 8; j++) tj[j] = aux[bn + tx * 8 + j];
#pragma unroll
        for (int i = 0; i < 8; i++) {
            size_t rowoff = (size_t)(bm + ty * 8 + i) * Nc + bn + tx * 8;
#pragma unroll
            for (int j = 0; j < 8; j++) {
                float a = fabsf(ti[i] - tj[j]) * (1.0f / TIME_DECAY_F);
                float bias = logf(expf(-a) + EPS_F);
                C[rowoff + j] = acc[i][j] * SCALE_INV + bias;
            }
        }
    }
}

// ============================================================
// GEMM NN: C[M,Nc] = A[M,K] @ B[K,Nc]   (row-major)
// Used for O = P @ V  (M=8192, K=8192, Nc=1024)
// ============================================================
__global__ __launch_bounds__(256)
void gemm_nn(const float* __restrict__ A,
             const float* __restrict__ B,
             float* __restrict__ C,
             int M, int Nc, int K)
{
    __shared__ float As[8][128];
    __shared__ float Bs[8][128];

    const int tid = threadIdx.x;
    const int tx = tid & 15;
    const int ty = tid >> 4;
    const int bm = blockIdx.y * 128;
    const int bn = blockIdx.x * 128;

    const int aRow = tid >> 1;
    const int aCol = (tid & 1) * 4;
    const int bRow = tid >> 5;           // 0..7
    const int bCol = (tid & 31) * 4;     // 0..124

    const float* Aptr = A + (size_t)(bm + aRow) * K + aCol;

    float acc[8][8];
#pragma unroll
    for (int i = 0; i < 8; i++)
#pragma unroll
        for (int j = 0; j < 8; j++) acc[i][j] = 0.0f;

    for (int k0 = 0; k0 < K; k0 += 8) {
        float4 a4 = *(const float4*)(Aptr + k0);
        float4 b4 = *(const float4*)(B + (size_t)(k0 + bRow) * Nc + bn + bCol);
        As[aCol + 0][aRow] = a4.x;
        As[aCol + 1][aRow] = a4.y;
        As[aCol + 2][aRow] = a4.z;
        As[aCol + 3][aRow] = a4.w;
        *(float4*)&Bs[bRow][bCol] = b4;
        __syncthreads();

#pragma unroll
        for (int k = 0; k < 8; k++) {
            float ra[8], rb[8];
#pragma unroll
            for (int i = 0; i < 8; i++) ra[i] = As[k][ty * 8 + i];
#pragma unroll
            for (int j = 0; j < 8; j++) rb[j] = Bs[k][tx * 8 + j];
#pragma unroll
            for (int i = 0; i < 8; i++)
#pragma unroll
                for (int j = 0; j < 8; j++)
                    acc[i][j] = fmaf(ra[i], rb[j], acc[i][j]);
        }
        __syncthreads();
    }

#pragma unroll
    for (int i = 0; i < 8; i++) {
        size_t rowoff = (size_t)(bm + ty * 8 + i) * Nc + bn + tx * 8;
#pragma unroll
        for (int j = 0; j < 8; j++)
            C[rowoff + j] = acc[i][j];
    }
}

// ============================================================
// Row softmax over g_S: one block per row, 256 threads,
// 32 elements/thread held in registers (N=8192).
// ============================================================
__global__ __launch_bounds__(256)
void softmax_rows(float* __restrict__ S, int n)
{
    const int row = blockIdx.x;
    float* p = S + (size_t)row * n;
    const int tid = threadIdx.x;

    float v[32];
    float m = -INFINITY;
#pragma unroll
    for (int i = 0; i < 32; i++) {
        v[i] = p[tid + i * 256];
        m = fmaxf(m, v[i]);
    }

    __shared__ float red[256];
    red[tid] = m;
    __syncthreads();
    for (int s = 128; s > 0; s >>= 1) {
        if (tid < s) red[tid] = fmaxf(red[tid], red[tid + s]);
        __syncthreads();
    }
    m = red[0];
    __syncthreads();

    float sum = 0.0f;
#pragma unroll
    for (int i = 0; i < 32; i++) {
        v[i] = expf(v[i] - m);
        sum += v[i];
    }
    red[tid] = sum;
    __syncthreads();
    for (int s = 128; s > 0; s >>= 1) {
        if (tid < s) red[tid] += red[tid + s];
        __syncthreads();
    }
    float inv = 1.0f / red[0];
    __syncthreads();

#pragma unroll
    for (int i = 0; i < 32; i++)
        p[tid + i * 256] = v[i] * inv;
}

// ============================================================
// kernel_launch
// inputs: 0:x [N,D] 1:timestamps [N] 2:Wq [D,D] 3:bq [D]
//         4:Wk 5:bk 6:Wv 7:bv      output: [N,D] fp32
// ============================================================
extern "C" void kernel_launch(void* const* d_in, const int* in_sizes, int n_in,
                              void* d_out, int out_size)
{
    const float* x  = (const float*)d_in[0];
    const float* ts = (const float*)d_in[1];
    const float* Wq = (const float*)d_in[2];
    const float* bq = (const float*)d_in[3];
    const float* Wk = (const float*)d_in[4];
    const float* bk = (const float*)d_in[5];
    const float* Wv = (const float*)d_in[6];
    const float* bv = (const float*)d_in[7];
    float* out = (float*)d_out;

    float *Qp, *Kp, *Vp, *Sp;
    cudaGetSymbolAddress((void**)&Qp, g_Q);
    cudaGetSymbolAddress((void**)&Kp, g_K);
    cudaGetSymbolAddress((void**)&Vp, g_V);
    cudaGetSymbolAddress((void**)&Sp, g_S);

    dim3 thr(256);

    // QKV projections: [8192,1024] = x[8192,1024] @ W^T + b
    {
        dim3 grid(D_DIM / 128, N_TOK / 128);   // (8, 64)
        gemm_nt<0><<<grid, thr>>>(x, Wq, bq, Qp, N_TOK, D_DIM, D_DIM);
        gemm_nt<0><<<grid, thr>>>(x, Wk, bk, Kp, N_TOK, D_DIM, D_DIM);
        gemm_nt<0><<<grid, thr>>>(x, Wv, bv, Vp, N_TOK, D_DIM, D_DIM);
    }

    // Scores: S = Q @ K^T / 32 + temporal bias
    {
        dim3 grid(N_TOK / 128, N_TOK / 128);   // (64, 64)
        gemm_nt<1><<<grid, thr>>>(Qp, Kp, ts, Sp, N_TOK, N_TOK, D_DIM);
    }

    // Softmax per row
    softmax_rows<<<N_TOK, thr>>>(Sp, N_TOK);

    // O = P @ V
    {
        dim3 grid(D_DIM / 128, N_TOK / 128);   // (8, 64)
        gemm_nn<<<grid, thr>>>(Sp, Vp, out, N_TOK, D_DIM, N_TOK);
    }
}